// round 13
// baseline (speedup 1.0000x reference)
#include <cuda_runtime.h>
#include <cuda_fp16.h>
#include <stdint.h>

// Problem dims (fixed)
#define T_STEPS 2048
#define BATCH   256
#define INP     256
#define HID     512
#define KH      512            // recurrent K (h only; x hoisted out)

#define JT 16                  // hidden cols per block
#define BT 64                  // batch rows per block
#define NBG 32                 // blocks per barrier group (one bTile)

// SMEM strides in words (all % 32 == 4 -> conflict-free ldmatrix rows)
#define WH_STRIDE 260          // K=512 fp16: 256 words + 4 pad
#define WI_STRIDE 132          // K=256 fp16: 128 words + 4 pad (precompute)
#define A_STRIDE  260
#define X_STRIDE  132
#define G_STRIDE  65

#define OFF_WHI 0
#define SZ_WH   (64 * WH_STRIDE * 4)          // 66,560
#define OFF_WLO SZ_WH
#define OFF_A   (2 * SZ_WH)                   // 133,120
#define SZ_A    (64 * A_STRIDE * 4)           // 66,560
#define OFF_GT  (OFF_A + SZ_A)                // 199,680
#define SZ_GT   (64 * G_STRIDE * 4)           // 16,640
#define SMEM_BYTES (OFF_GT + SZ_GT + 32)      // 216,352

// Persistent state
__device__ uint32_t g_h[2][BATCH * HID / 2];          // h as half2 words
__device__ float    g_hf[BATCH * HID];                // fp32 h for decode
__device__ __align__(128) volatile unsigned g_flag[4][32];   // per-group barrier lines
// Precomputed x-gates (+bias), fp16, MMA-fragment layout: [block][t][warp][lane][16]
__device__ __align__(16) __half g_xg[(size_t)128 * T_STEPS * 4096];

__device__ __forceinline__ uint32_t h2u(__half2 v) {
    return *reinterpret_cast<uint32_t*>(&v);
}
__device__ __forceinline__ float fast_sigmoid(float x) {
    x = fminf(fmaxf(x, -30.f), 30.f);
    return __fdividef(1.f, 1.f + __expf(-x));
}
__device__ __forceinline__ float fast_tanh(float x) {
    x = fminf(fmaxf(x, -15.f), 15.f);
    float e = __expf(2.f * x);
    return __fdividef(e - 1.f, e + 1.f);
}
__device__ __forceinline__ void ldsm4(uint32_t* r, uint32_t saddr) {
    asm volatile("ldmatrix.sync.aligned.m8n8.x4.shared.b16 {%0,%1,%2,%3}, [%4];"
                 : "=r"(r[0]), "=r"(r[1]), "=r"(r[2]), "=r"(r[3]) : "r"(saddr));
}
__device__ __forceinline__ void addh2(float& a, float& b, uint32_t w) {
    float2 f = __half22float2(*reinterpret_cast<__half2*>(&w));
    a += f.x; b += f.y;
}
#define MMA_F16(D, A, B0, B1)                                               \
    asm volatile("mma.sync.aligned.m16n8k16.row.col.f32.f16.f16.f32 "       \
                 "{%0,%1,%2,%3}, {%4,%5,%6,%7}, {%8,%9}, {%0,%1,%2,%3};"    \
                 : "+f"((D)[0]), "+f"((D)[1]), "+f"((D)[2]), "+f"((D)[3])   \
                 : "r"((A)[0]), "r"((A)[1]), "r"((A)[2]), "r"((A)[3]),      \
                   "r"(B0), "r"(B1));

// ONE kernel: precompute x-gates + init + 2048 fused steps + decode.
// Grid (32, 4) x 256 threads, all co-resident.
__global__ __launch_bounds__(256, 1)
void lstm_xg_kernel(const float* __restrict__ x_all,
                    const float* __restrict__ h0,
                    const float* __restrict__ c0,
                    const float* __restrict__ W_ih,
                    const float* __restrict__ W_hh,
                    const float* __restrict__ b_ih,
                    const float* __restrict__ b_hh,
                    const float* __restrict__ W_dec,
                    const float* __restrict__ b_dec,
                    float* __restrict__ out)
{
    extern __shared__ __align__(16) char sm[];
    uint32_t* Whi   = (uint32_t*)(sm + OFF_WHI);
    uint32_t* Wlo   = (uint32_t*)(sm + OFF_WLO);
    uint32_t* Ab    = (uint32_t*)(sm + OFF_A);
    float*    gates = (float*)   (sm + OFF_GT);
    __shared__ unsigned s_base;

    const int tid  = threadIdx.x;
    const int lane = tid & 31, warp = tid >> 5;
    const int wm = warp & 1;         // batch half of 64x64 tile
    const int wn = warp >> 1;        // 16-gatecol slice
    const int jTile = blockIdx.x;    // 0..31
    const int bTile = blockIdx.y;    // 0..3 (= barrier group)
    const int bid   = bTile * 32 + jTile;

    if (tid == 0) s_base = g_flag[bTile][jTile];   // own flag: race-free, replay-safe

    // ---- per-thread bias fragment (n = wn*16 + nf*8 + (lane&3)*2 + e) ----
    float bfr[2][2];
#pragma unroll
    for (int nf = 0; nf < 2; ++nf)
#pragma unroll
        for (int e = 0; e < 2; ++e) {
            int n  = wn * 16 + nf * 8 + (lane & 3) * 2 + e;
            int gr = (n >> 4) * HID + jTile * JT + (n & 15);
            bfr[nf][e] = b_ih[gr] + b_hh[gr];
        }

    // ---- load W_ih slice split hi/lo (K=256, stride 132) for precompute ----
    {
        int r = tid >> 2;
        int grow = (r >> 4) * HID + jTile * JT + (r & 15);
        int kbase = (tid & 3) * 64;
        for (int i = 0; i < 32; ++i) {
            int k = kbase + 2 * i;
            float2 v = *(const float2*)(W_ih + (size_t)grow * INP + k);
            __half hx = __float2half_rn(v.x), hy = __float2half_rn(v.y);
            __half lx = __float2half_rn(v.x - __half2float(hx));
            __half ly = __float2half_rn(v.y - __half2float(hy));
            Whi[r * WI_STRIDE + k / 2] = h2u(__halves2half2(hx, hy));
            Wlo[r * WI_STRIDE + k / 2] = h2u(__halves2half2(lx, ly));
        }
    }

    // ---- epilogue ownership + h/c init ----
    const int eb  = tid >> 2;
    const int ebg = bTile * BT + eb;
    const int ej0 = (tid & 3) * 4;
    const int jg0 = jTile * JT + ej0;
    const int hwi = ebg * (HID / 2) + jg0 / 2;
    float creg[4];
    {
        float4 cv = *(const float4*)(c0 + (size_t)ebg * HID + jg0);
        creg[0] = cv.x; creg[1] = cv.y; creg[2] = cv.z; creg[3] = cv.w;
        float4 hv = *(const float4*)(h0 + (size_t)ebg * HID + jg0);
        *(uint2*)&g_h[0][hwi] = make_uint2(h2u(__floats2half2_rn(hv.x, hv.y)),
                                           h2u(__floats2half2_rn(hv.z, hv.w)));
    }
    __syncthreads();
    const unsigned fbase = s_base;
    unsigned seq = 0;

    // ---- ldmatrix lane bases ----
    const uint32_t a_sh   = (uint32_t)__cvta_generic_to_shared(Ab);
    const uint32_t whi_sh = (uint32_t)__cvta_generic_to_shared(Whi);
    const uint32_t wlo_sh = (uint32_t)__cvta_generic_to_shared(Wlo);
    const int rowoff = (lane & 7) + ((lane >> 3) & 1) * 8;
    const int khalf4 = (lane >> 4) * 4;
    // precompute-phase (stride 132)
    const uint32_t wpi = whi_sh + ((wn * 16 + rowoff) * WI_STRIDE + khalf4) * 4;
    const uint32_t wpl = wlo_sh + ((wn * 16 + rowoff) * WI_STRIDE + khalf4) * 4;
    uint32_t api[2];
#pragma unroll
    for (int mf = 0; mf < 2; ++mf)
        api[mf] = a_sh + ((wm * 32 + mf * 16 + rowoff) * X_STRIDE + khalf4) * 4;

    // staging map: 4 threads per row
    const int srow  = tid >> 2;
    const int sq    = tid & 3;
    const int sbrow = bTile * BT + srow;

    const size_t xgbase = ((size_t)bid * T_STEPS) * 4096 + warp * 512 + lane * 16;

    // ======== PHASE 1: precompute xg[t] = x_t @ W_ih^T + bias (block-local) ========
    for (int t = 0; t < T_STEPS; ++t) {
        // stage x[t, block rows, 0..255] -> fp16 SMEM (stride 132)
        {
            const float4* src = (const float4*)(x_all + ((size_t)t * BATCH + sbrow) * INP + sq * 64);
#pragma unroll
            for (int i = 0; i < 8; ++i) {
                float4 f = src[2 * i];
                float4 g = src[2 * i + 1];
                *(uint4*)&Ab[srow * X_STRIDE + sq * 32 + i * 4] =
                    make_uint4(h2u(__floats2half2_rn(f.x, f.y)),
                               h2u(__floats2half2_rn(f.z, f.w)),
                               h2u(__floats2half2_rn(g.x, g.y)),
                               h2u(__floats2half2_rn(g.z, g.w)));
            }
        }
        __syncthreads();

        float d[2][2][4];
#pragma unroll
        for (int mf = 0; mf < 2; ++mf)
#pragma unroll
            for (int nf = 0; nf < 2; ++nf)
#pragma unroll
                for (int q = 0; q < 4; ++q) d[mf][nf][q] = 0.f;

#pragma unroll 4
        for (int ks = 0; ks < 16; ++ks) {
            const uint32_t s32 = (uint32_t)(ks * 32);
            uint32_t bh[4], bl[4];
            ldsm4(bh, wpi + s32);
            ldsm4(bl, wpl + s32);
#pragma unroll
            for (int mf = 0; mf < 2; ++mf) {
                uint32_t a[4];
                ldsm4(a, api[mf] + s32);
                MMA_F16(d[mf][0], a, bh[0], bh[2]);
                MMA_F16(d[mf][1], a, bh[1], bh[3]);
                MMA_F16(d[mf][0], a, bl[0], bl[2]);
                MMA_F16(d[mf][1], a, bl[1], bl[3]);
            }
        }

        // pack (+bias) -> fp16 fragments -> global (coalesced 32B/thread)
        uint32_t pk[8];
#pragma unroll
        for (int mf = 0; mf < 2; ++mf)
#pragma unroll
            for (int nf = 0; nf < 2; ++nf) {
                pk[mf * 4 + nf * 2 + 0] = h2u(__floats2half2_rn(
                    d[mf][nf][0] + bfr[nf][0], d[mf][nf][1] + bfr[nf][1]));
                pk[mf * 4 + nf * 2 + 1] = h2u(__floats2half2_rn(
                    d[mf][nf][2] + bfr[nf][0], d[mf][nf][3] + bfr[nf][1]));
            }
        uint4* dst = (uint4*)(g_xg + xgbase + (size_t)t * 4096);
        dst[0] = make_uint4(pk[0], pk[1], pk[2], pk[3]);
        dst[1] = make_uint4(pk[4], pk[5], pk[6], pk[7]);
        __syncthreads();
    }

    // ---- swap W planes: load W_hh split hi/lo (K=512, stride 260) ----
    {
        int r = tid >> 2;
        int grow = (r >> 4) * HID + jTile * JT + (r & 15);
        int kbase = (tid & 3) * 128;
        for (int i = 0; i < 64; ++i) {
            int k = kbase + 2 * i;
            float2 v = *(const float2*)(W_hh + (size_t)grow * HID + k);
            __half hx = __float2half_rn(v.x), hy = __float2half_rn(v.y);
            __half lx = __float2half_rn(v.x - __half2float(hx));
            __half ly = __float2half_rn(v.y - __half2float(hy));
            Whi[r * WH_STRIDE + k / 2] = h2u(__halves2half2(hx, hy));
            Wlo[r * WH_STRIDE + k / 2] = h2u(__halves2half2(lx, ly));
        }
    }

    // loop-phase lane bases (stride 260)
    const uint32_t wli = whi_sh + ((wn * 16 + rowoff) * WH_STRIDE + khalf4) * 4;
    const uint32_t wll = wlo_sh + ((wn * 16 + rowoff) * WH_STRIDE + khalf4) * 4;
    uint32_t ali[2];
#pragma unroll
    for (int mf = 0; mf < 2; ++mf)
        ali[mf] = a_sh + ((wm * 32 + mf * 16 + rowoff) * A_STRIDE + khalf4) * 4;

    // flag barrier (parallel STGs to one 128B line per group; monotonic values)
#define GROUP_BARRIER()                                                     \
    do {                                                                    \
        __syncthreads();                                                    \
        ++seq;                                                              \
        if (tid == 0) { __threadfence(); g_flag[bTile][jTile] = fbase + seq; } \
        if (tid < 32) {                                                     \
            while (g_flag[bTile][tid] < fbase + seq) { }                    \
            __threadfence();                                                \
        }                                                                   \
        __syncthreads();                                                    \
    } while (0)

    GROUP_BARRIER();   // publish h init (and separate precompute skew)

    // ======== PHASE 2: 2048 recurrent steps (K = 512, h only) ========
    for (int t = 0; t < T_STEPS; ++t) {
        const uint32_t* __restrict__ h_in = g_h[t & 1];
        uint32_t* __restrict__ h_out = g_h[(t & 1) ^ 1];

        // prefetch xg fragments (independent of staging)
        const uint4* xp = (const uint4*)(g_xg + xgbase + (size_t)t * 4096);
        uint4 xa = xp[0], xb = xp[1];

        // stage h tile: 64 rows x 512 halves (direct fp16 copy)
        {
            const uint4* hsrc = (const uint4*)(h_in + sbrow * (HID / 2) + sq * 64);
#pragma unroll
            for (int i = 0; i < 16; ++i)
                *(uint4*)&Ab[srow * A_STRIDE + sq * 64 + i * 4] = hsrc[i];
        }
        __syncthreads();

        float d[2][2][4];
#pragma unroll
        for (int mf = 0; mf < 2; ++mf)
#pragma unroll
            for (int nf = 0; nf < 2; ++nf)
#pragma unroll
                for (int q = 0; q < 4; ++q) d[mf][nf][q] = 0.f;

#pragma unroll 8
        for (int ks = 0; ks < 32; ++ks) {
            const uint32_t s32 = (uint32_t)(ks * 32);
            uint32_t bh[4], bl[4];
            ldsm4(bh, wli + s32);
            ldsm4(bl, wll + s32);
#pragma unroll
            for (int mf = 0; mf < 2; ++mf) {
                uint32_t a[4];
                ldsm4(a, ali[mf] + s32);
                MMA_F16(d[mf][0], a, bh[0], bh[2]);
                MMA_F16(d[mf][1], a, bh[1], bh[3]);
                MMA_F16(d[mf][0], a, bl[0], bl[2]);
                MMA_F16(d[mf][1], a, bl[1], bl[3]);
            }
        }

        // add precomputed x-gates (+bias) fragments
        addh2(d[0][0][0], d[0][0][1], xa.x);
        addh2(d[0][0][2], d[0][0][3], xa.y);
        addh2(d[0][1][0], d[0][1][1], xa.z);
        addh2(d[0][1][2], d[0][1][3], xa.w);
        addh2(d[1][0][0], d[1][0][1], xb.x);
        addh2(d[1][0][2], d[1][0][3], xb.y);
        addh2(d[1][1][0], d[1][1][1], xb.z);
        addh2(d[1][1][2], d[1][1][3], xb.w);

        // spill to dedicated gates buffer (no conflict with A tile)
        {
            const int lq = lane >> 2, lr4 = lane & 3;
#pragma unroll
            for (int mf = 0; mf < 2; ++mf)
#pragma unroll
                for (int nf = 0; nf < 2; ++nf) {
                    int m = wm * 32 + mf * 16 + lq;
                    int n = wn * 16 + nf * 8 + lr4 * 2;
                    gates[ m      * G_STRIDE + n    ] = d[mf][nf][0];
                    gates[ m      * G_STRIDE + n + 1] = d[mf][nf][1];
                    gates[(m + 8) * G_STRIDE + n    ] = d[mf][nf][2];
                    gates[(m + 8) * G_STRIDE + n + 1] = d[mf][nf][3];
                }
        }
        __syncthreads();

        // LSTM epilogue (bias already inside xg)
        {
            float hnew[4];
#pragma unroll
            for (int i = 0; i < 4; ++i) {
                int j = ej0 + i;
                float gi = gates[eb * G_STRIDE + j];
                float gf = gates[eb * G_STRIDE + 16 + j];
                float gg = gates[eb * G_STRIDE + 32 + j];
                float go = gates[eb * G_STRIDE + 48 + j];
                float iv = fast_sigmoid(gi);
                float fv = fast_sigmoid(gf);
                float gv = fast_tanh(gg);
                float ov = fast_sigmoid(go);
                float cn = fv * creg[i] + iv * gv;
                creg[i] = cn;
                hnew[i] = ov * fast_tanh(cn);
            }
            *(uint2*)&h_out[hwi] =
                make_uint2(h2u(__floats2half2_rn(hnew[0], hnew[1])),
                           h2u(__floats2half2_rn(hnew[2], hnew[3])));
            if (t == T_STEPS - 1)
                *(float4*)&g_hf[(size_t)ebg * HID + jg0] =
                    make_float4(hnew[0], hnew[1], hnew[2], hnew[3]);
        }

        GROUP_BARRIER();
    }

    // ======== decode by jTile==0 blocks ========
    if (jTile == 0) {
        int b = bTile * BT + (tid >> 2);
        int part = tid & 3;
        const float* hb = g_hf + (size_t)b * HID + part * 128;
        const float* wd = W_dec + part * 128;
        float s = 0.f;
#pragma unroll 8
        for (int i = 0; i < 128; ++i) s = fmaf(hb[i], wd[i], s);
        s += __shfl_down_sync(0xFFFFFFFF, s, 2, 4);
        s += __shfl_down_sync(0xFFFFFFFF, s, 1, 4);
        if (part == 0) out[b] = s + b_dec[0];
    }
#undef GROUP_BARRIER
}

extern "C" void kernel_launch(void* const* d_in, const int* in_sizes, int n_in,
                              void* d_out, int out_size)
{
    (void)in_sizes; (void)n_in; (void)out_size;
    const float* x     = (const float*)d_in[0];
    const float* h0    = (const float*)d_in[1];
    const float* c0    = (const float*)d_in[2];
    const float* W_ih  = (const float*)d_in[3];
    const float* W_hh  = (const float*)d_in[4];
    const float* b_ih  = (const float*)d_in[5];
    const float* b_hh  = (const float*)d_in[6];
    const float* W_dec = (const float*)d_in[7];
    const float* b_dec = (const float*)d_in[8];
    float* out = (float*)d_out;

    static bool attr_set = false;
    if (!attr_set) {
        cudaFuncSetAttribute(lstm_xg_kernel,
                             cudaFuncAttributeMaxDynamicSharedMemorySize, SMEM_BYTES);
        attr_set = true;
    }

    dim3 grid(HID / JT, BATCH / BT);   // (32, 4) = 128 blocks, all co-resident
    lstm_xg_kernel<<<grid, 256, SMEM_BYTES>>>(x, h0, c0, W_ih, W_hh,
                                              b_ih, b_hh, W_dec, b_dec, out);
}

// round 14
// speedup vs baseline: 2.2396x; 2.2396x over previous
#include <cuda_runtime.h>
#include <cuda_fp16.h>
#include <stdint.h>

// Problem dims (fixed)
#define T_STEPS 2048
#define BATCH   256
#define INP     256
#define HID     512
#define KTOT    768

// Block = (jTile 0..31, bTile 0..3): 16 hidden cols x 64 batch rows; 128 blocks
#define JT 16
#define BT 64
#define KC 64                  // k elems per staged chunk
#define NCH (KTOT / KC)        // 12 chunks (0-3: x, 4-11: h)
#define NBG 32                 // blocks per barrier group (one bTile)

// SMEM strides in 32-bit words (stride % 32 == 4 -> conflict-free ldmatrix rows)
#define W_STRIDE 388           // 768 fp16 = 384 words + 4 pad
#define A_STRIDE 36            // 64 fp16  = 32 words + 4 pad
#define G_STRIDE 65
#define ABUF_WORDS (BT * A_STRIDE)     // 2304
#define ABUF_BYTES (ABUF_WORDS * 4)    // 9216

#define OFF_W   0
#define SZ_W    (64 * W_STRIDE * 4)            // 99,328 (single fp16 plane)
#define OFF_A   SZ_W                           // 99,328
#define OFF_GT  (OFF_A + 2 * ABUF_BYTES)       // 117,760 (dedicated gates buffer)
#define SZ_GT   (64 * G_STRIDE * 4)            // 16,640
#define OFF_BIAS (OFF_GT + SZ_GT)              // 134,400
#define SMEM_BYTES (OFF_BIAS + 256 + 16)       // 134,672

// Persistent state: h as packed half2 words, double-buffered; fp32 copy for decode
__device__ uint32_t g_h[2][BATCH * HID / 2];
__device__ float    g_hf[BATCH * HID];
__device__ __align__(128) volatile unsigned g_flag[4][32];   // per-group barrier lines

__device__ __forceinline__ uint32_t h2u(__half2 v) {
    return *reinterpret_cast<uint32_t*>(&v);
}
__device__ __forceinline__ float fast_sigmoid(float x) {
    x = fminf(fmaxf(x, -30.f), 30.f);
    return __fdividef(1.f, 1.f + __expf(-x));
}
__device__ __forceinline__ float fast_tanh(float x) {
    x = fminf(fmaxf(x, -15.f), 15.f);
    float e = __expf(2.f * x);
    return __fdividef(e - 1.f, e + 1.f);
}
__device__ __forceinline__ void ldsm4(uint32_t* r, uint32_t saddr) {
    asm volatile("ldmatrix.sync.aligned.m8n8.x4.shared.b16 {%0,%1,%2,%3}, [%4];"
                 : "=r"(r[0]), "=r"(r[1]), "=r"(r[2]), "=r"(r[3]) : "r"(saddr));
}
#define MMA_F16(D, A, B0, B1)                                               \
    asm volatile("mma.sync.aligned.m16n8k16.row.col.f32.f16.f16.f32 "       \
                 "{%0,%1,%2,%3}, {%4,%5,%6,%7}, {%8,%9}, {%0,%1,%2,%3};"    \
                 : "+f"((D)[0]), "+f"((D)[1]), "+f"((D)[2]), "+f"((D)[3])   \
                 : "r"((A)[0]), "r"((A)[1]), "r"((A)[2]), "r"((A)[3]),      \
                   "r"(B0), "r"(B1));

// ONE kernel: init + 2048 fused steps + decode. Grid (32, 4) x 256 threads.
__global__ __launch_bounds__(256, 1)
void lstm_fp16s_kernel(const float* __restrict__ x_all,
                       const float* __restrict__ h0,
                       const float* __restrict__ c0,
                       const float* __restrict__ W_ih,
                       const float* __restrict__ W_hh,
                       const float* __restrict__ b_ih,
                       const float* __restrict__ b_hh,
                       const float* __restrict__ W_dec,
                       const float* __restrict__ b_dec,
                       float* __restrict__ out)
{
    extern __shared__ __align__(16) char sm[];
    uint32_t* W     = (uint32_t*)(sm + OFF_W);
    uint32_t* Ab    = (uint32_t*)(sm + OFF_A);
    float*    gates = (float*)   (sm + OFF_GT);
    float*    bias_s = (float*)  (sm + OFF_BIAS);
    __shared__ unsigned s_base;

    const int tid  = threadIdx.x;
    const int lane = tid & 31, warp = tid >> 5;
    const int wm = warp & 1;        // batch half (32 rows)
    const int wn = warp >> 1;       // 16-gatecol slice (0..3)
    const int jTile = blockIdx.x;   // 0..31
    const int bTile = blockIdx.y;   // 0..3 (= barrier group)

    if (tid == 0) s_base = g_flag[bTile][jTile];   // replay-safe monotonic base

    // ---- one-time: weights -> SMEM, single fp16 plane (K-major, padded) ----
    {
        int r = tid >> 2;                        // weight row 0..63 (tt*16+jj)
        int grow = (r >> 4) * HID + jTile * JT + (r & 15);
        int kbase = (tid & 3) * 192;
        for (int i = 0; i < 96; ++i) {
            int k = kbase + 2 * i;
            float2 v = (k < INP)
                ? *(const float2*)(W_ih + (size_t)grow * INP + k)
                : *(const float2*)(W_hh + (size_t)grow * HID + (k - INP));
            W[r * W_STRIDE + k / 2] = h2u(__floats2half2_rn(v.x, v.y));
        }
        if (tid < 64) {
            int gr = (tid >> 4) * HID + jTile * JT + (tid & 15);
            bias_s[tid] = b_ih[gr] + b_hh[gr];
        }
    }

    // ---- epilogue ownership: thread owns (eb, ej0..ej0+3); c in registers ----
    const int eb  = tid >> 2;
    const int ebg = bTile * BT + eb;
    const int ej0 = (tid & 3) * 4;
    const int jg0 = jTile * JT + ej0;
    const int hwi = ebg * (HID / 2) + jg0 / 2;   // half2-word index
    float creg[4];
    {
        float4 cv = *(const float4*)(c0 + (size_t)ebg * HID + jg0);
        creg[0] = cv.x; creg[1] = cv.y; creg[2] = cv.z; creg[3] = cv.w;
        float4 hv = *(const float4*)(h0 + (size_t)ebg * HID + jg0);
        *(uint2*)&g_h[0][hwi] = make_uint2(h2u(__floats2half2_rn(hv.x, hv.y)),
                                           h2u(__floats2half2_rn(hv.z, hv.w)));
    }
    __syncthreads();
    const unsigned fbase = s_base;
    unsigned seq = 0;

    // arrive: publish h; wait deferred (hidden behind x-chunk work)
#define GROUP_ARRIVE()                                                      \
    do {                                                                    \
        __syncthreads();                                                    \
        ++seq;                                                              \
        if (tid == 0) { __threadfence(); g_flag[bTile][jTile] = fbase + seq; } \
    } while (0)
#define GROUP_WAIT()                                                        \
    do {                                                                    \
        if (tid < 32) {                                                     \
            while (g_flag[bTile][tid] - fbase < seq) { }                    \
            __threadfence();                                                \
        }                                                                   \
        __syncthreads();                                                    \
    } while (0)

    GROUP_ARRIVE();   // publish h init (seq = 1)

    // ---- ldmatrix lane addressing (bytes, shared space) ----
    const uint32_t a_sh = (uint32_t)__cvta_generic_to_shared(Ab);
    const uint32_t w_sh = (uint32_t)__cvta_generic_to_shared(W);
    const int rowoff = (lane & 7) + ((lane >> 3) & 1) * 8;
    const int khalf4 = (lane >> 4) * 4;          // word offset for k-half
    const uint32_t wlane = w_sh + ((wn * 16 + rowoff) * W_STRIDE + khalf4) * 4;
    uint32_t alane[2];
#pragma unroll
    for (int mf = 0; mf < 2; ++mf)
        alane[mf] = a_sh + ((wm * 32 + mf * 16 + rowoff) * A_STRIDE + khalf4) * 4;

    // staging: 4 threads per batch row, 16 k elems (8 half2 words) each
    const int srow = tid >> 2;
    const int sq   = tid & 3;
    const int sbrow = bTile * BT + srow;
    const int sdst  = srow * A_STRIDE + sq * 8;  // word offset in A plane

    for (int t = 0; t < T_STEPS; ++t) {
        const float* __restrict__ x_t = x_all + (size_t)t * BATCH * INP;
        const uint32_t* __restrict__ h_in = g_h[t & 1];
        uint32_t* __restrict__ h_out = g_h[(t & 1) ^ 1];

        float d[2][2][4];
#pragma unroll
        for (int mf = 0; mf < 2; ++mf)
#pragma unroll
            for (int nf = 0; nf < 2; ++nf)
#pragma unroll
                for (int q = 0; q < 4; ++q) d[mf][nf][q] = 0.f;

        // ---- stage chunk 0 (pure x) into buf 0 ----
        {
            const float* src = x_t + (size_t)sbrow * INP + sq * 16;
            float4 f0 = *(const float4*)(src);
            float4 f1 = *(const float4*)(src + 4);
            float4 f2 = *(const float4*)(src + 8);
            float4 f3 = *(const float4*)(src + 12);
            *(uint4*)&Ab[sdst] = make_uint4(h2u(__floats2half2_rn(f0.x, f0.y)),
                                            h2u(__floats2half2_rn(f0.z, f0.w)),
                                            h2u(__floats2half2_rn(f1.x, f1.y)),
                                            h2u(__floats2half2_rn(f1.z, f1.w)));
            *(uint4*)&Ab[sdst + 4] = make_uint4(h2u(__floats2half2_rn(f2.x, f2.y)),
                                                h2u(__floats2half2_rn(f2.z, f2.w)),
                                                h2u(__floats2half2_rn(f3.x, f3.y)),
                                                h2u(__floats2half2_rn(f3.z, f3.w)));
        }
        __syncthreads();

        int buf = 0;
        for (int c = 0; c < NCH; ++c) {
            // deferred barrier wait: h needed first by chunk 4's prefetch
            if (c == 3) GROUP_WAIT();

            // ---- prefetch chunk c+1 ----
            uint4 pa, pb;
            bool have_next = (c < NCH - 1);
            if (have_next) {
                int cn = c + 1;
                if (cn < 4) {   // x chunk: LDG fp32 + cvt
                    const float* src = x_t + (size_t)sbrow * INP + cn * KC + sq * 16;
                    float4 f0 = *(const float4*)(src);
                    float4 f1 = *(const float4*)(src + 4);
                    float4 f2 = *(const float4*)(src + 8);
                    float4 f3 = *(const float4*)(src + 12);
                    pa = make_uint4(h2u(__floats2half2_rn(f0.x, f0.y)),
                                    h2u(__floats2half2_rn(f0.z, f0.w)),
                                    h2u(__floats2half2_rn(f1.x, f1.y)),
                                    h2u(__floats2half2_rn(f1.z, f1.w)));
                    pb = make_uint4(h2u(__floats2half2_rn(f2.x, f2.y)),
                                    h2u(__floats2half2_rn(f2.z, f2.w)),
                                    h2u(__floats2half2_rn(f3.x, f3.y)),
                                    h2u(__floats2half2_rn(f3.z, f3.w)));
                } else {        // h chunk: already fp16 words
                    int widx = sbrow * (HID / 2) + (cn - 4) * 32 + sq * 8;
                    pa = *(const uint4*)&h_in[widx];
                    pb = *(const uint4*)&h_in[widx + 4];
                }
            }

            // ---- MMAs on chunk c: 4 k16-slices, single W plane ----
            const uint32_t aoff = (uint32_t)(buf * ABUF_BYTES);
#pragma unroll
            for (int ks = 0; ks < 4; ++ks) {
                const uint32_t s32 = (uint32_t)((c * 4 + ks) * 32);
                uint32_t bw[4];
                ldsm4(bw, wlane + s32);
#pragma unroll
                for (int mf = 0; mf < 2; ++mf) {
                    uint32_t a[4];
                    ldsm4(a, alane[mf] + aoff + (uint32_t)(ks * 32));
                    MMA_F16(d[mf][0], a, bw[0], bw[2]);
                    MMA_F16(d[mf][1], a, bw[1], bw[3]);
                }
            }

            // ---- commit prefetched chunk ----
            if (have_next) {
                int nb = buf ^ 1;
                *(uint4*)&Ab[nb * ABUF_WORDS + sdst]     = pa;
                *(uint4*)&Ab[nb * ABUF_WORDS + sdst + 4] = pb;
            }
            __syncthreads();
            buf ^= 1;
        }

        // ---- spill accumulators to dedicated gates buffer ----
        {
            const int lq = lane >> 2, lr4 = lane & 3;
#pragma unroll
            for (int mf = 0; mf < 2; ++mf)
#pragma unroll
                for (int nf = 0; nf < 2; ++nf) {
                    int m = wm * 32 + mf * 16 + lq;
                    int n = wn * 16 + nf * 8 + lr4 * 2;
                    gates[ m      * G_STRIDE + n    ] = d[mf][nf][0];
                    gates[ m      * G_STRIDE + n + 1] = d[mf][nf][1];
                    gates[(m + 8) * G_STRIDE + n    ] = d[mf][nf][2];
                    gates[(m + 8) * G_STRIDE + n + 1] = d[mf][nf][3];
                }
        }
        __syncthreads();

        // ---- LSTM epilogue: c in regs, h stored fp16 (fp32 copy on last step) ----
        {
            float hnew[4];
#pragma unroll
            for (int i = 0; i < 4; ++i) {
                int j = ej0 + i;
                float gi = gates[eb * G_STRIDE + j]      + bias_s[j];
                float gf = gates[eb * G_STRIDE + 16 + j] + bias_s[16 + j];
                float gg = gates[eb * G_STRIDE + 32 + j] + bias_s[32 + j];
                float go = gates[eb * G_STRIDE + 48 + j] + bias_s[48 + j];
                float iv = fast_sigmoid(gi);
                float fv = fast_sigmoid(gf);
                float gv = fast_tanh(gg);
                float ov = fast_sigmoid(go);
                float cn = fv * creg[i] + iv * gv;
                creg[i] = cn;
                hnew[i] = ov * fast_tanh(cn);
            }
            *(uint2*)&h_out[hwi] =
                make_uint2(h2u(__floats2half2_rn(hnew[0], hnew[1])),
                           h2u(__floats2half2_rn(hnew[2], hnew[3])));
            if (t == T_STEPS - 1)
                *(float4*)&g_hf[(size_t)ebg * HID + jg0] =
                    make_float4(hnew[0], hnew[1], hnew[2], hnew[3]);
        }

        GROUP_ARRIVE();   // publish h; next step's x chunks hide the wait
    }

    GROUP_WAIT();         // final h published everywhere (for decode)

    // ---- decode by jTile==0 blocks from the fp32 h copy ----
    if (jTile == 0) {
        int b = bTile * BT + (tid >> 2);
        int part = tid & 3;
        const float* hb = g_hf + (size_t)b * HID + part * 128;
        const float* wd = W_dec + part * 128;
        float s = 0.f;
#pragma unroll 8
        for (int i = 0; i < 128; ++i) s = fmaf(hb[i], wd[i], s);
        s += __shfl_down_sync(0xFFFFFFFF, s, 2, 4);
        s += __shfl_down_sync(0xFFFFFFFF, s, 1, 4);
        if (part == 0) out[b] = s + b_dec[0];
    }
#undef GROUP_ARRIVE
#undef GROUP_WAIT
}

extern "C" void kernel_launch(void* const* d_in, const int* in_sizes, int n_in,
                              void* d_out, int out_size)
{
    (void)in_sizes; (void)n_in; (void)out_size;
    const float* x     = (const float*)d_in[0];
    const float* h0    = (const float*)d_in[1];
    const float* c0    = (const float*)d_in[2];
    const float* W_ih  = (const float*)d_in[3];
    const float* W_hh  = (const float*)d_in[4];
    const float* b_ih  = (const float*)d_in[5];
    const float* b_hh  = (const float*)d_in[6];
    const float* W_dec = (const float*)d_in[7];
    const float* b_dec = (const float*)d_in[8];
    float* out = (float*)d_out;

    static bool attr_set = false;
    if (!attr_set) {
        cudaFuncSetAttribute(lstm_fp16s_kernel,
                             cudaFuncAttributeMaxDynamicSharedMemorySize, SMEM_BYTES);
        attr_set = true;
    }

    dim3 grid(HID / JT, BATCH / BT);   // (32, 4) = 128 blocks, all co-resident
    lstm_fp16s_kernel<<<grid, 256, SMEM_BYTES>>>(x, h0, c0, W_ih, W_hh,
                                                 b_ih, b_hh, W_dec, b_dec, out);
}

// round 15
// speedup vs baseline: 2.6857x; 1.1992x over previous
#include <cuda_runtime.h>
#include <cuda_fp16.h>
#include <stdint.h>

// Problem dims (fixed)
#define T_STEPS 2048
#define BATCH   256
#define INP     256
#define HID     512
#define KTOT    768

// Block = (jTile 0..31, bTile 0..3): 16 hidden cols x 64 batch rows; 128 blocks
#define JT 16
#define BT 64
#define THREADS 512            // 16 warps: kg(2) x wn(4) x wm(2)
#define KC 128                 // k elems per staged chunk
#define NCH (KTOT / KC)        // 6 chunks (0-1: x, 2-5: h)
#define NBG 32                 // blocks per barrier group (one bTile)

// SMEM strides in 32-bit words (row byte-stride % 128 == 16 -> conflict-free ldsm)
#define W_STRIDE 388           // 768 fp16 = 384 words + 4 pad
#define A_STRIDE 68            // 128 fp16 = 64 words + 4 pad
#define G_STRIDE 65
#define GT_WORDS (64 * G_STRIDE)
#define ABUF_WORDS (BT * A_STRIDE)     // 4352
#define ABUF_BYTES (ABUF_WORDS * 4)    // 17408

#define OFF_W    0
#define SZ_W     (64 * W_STRIDE * 4)           // 99,328 (single fp16 plane)
#define OFF_A    SZ_W                          // 99,328
#define OFF_GT   (OFF_A + 2 * ABUF_BYTES)      // 134,144 (2 split-K gate buffers)
#define OFF_BIAS (OFF_GT + 2 * GT_WORDS * 4)   // 167,424
#define SMEM_BYTES (OFF_BIAS + 256 + 16)       // 167,696

// Persistent state: h as packed half2 words, double-buffered; fp32 copy for decode
__device__ uint32_t g_h[2][BATCH * HID / 2];
__device__ float    g_hf[BATCH * HID];
__device__ __align__(128) volatile unsigned g_flag[4][32];   // per-group barrier lines

__device__ __forceinline__ uint32_t h2u(__half2 v) {
    return *reinterpret_cast<uint32_t*>(&v);
}
__device__ __forceinline__ float fast_sigmoid(float x) {
    x = fminf(fmaxf(x, -30.f), 30.f);
    return __fdividef(1.f, 1.f + __expf(-x));
}
__device__ __forceinline__ float fast_tanh(float x) {
    x = fminf(fmaxf(x, -15.f), 15.f);
    float e = __expf(2.f * x);
    return __fdividef(e - 1.f, e + 1.f);
}
__device__ __forceinline__ void ldsm4(uint32_t* r, uint32_t saddr) {
    asm volatile("ldmatrix.sync.aligned.m8n8.x4.shared.b16 {%0,%1,%2,%3}, [%4];"
                 : "=r"(r[0]), "=r"(r[1]), "=r"(r[2]), "=r"(r[3]) : "r"(saddr));
}
#define MMA_F16(D, A, B0, B1)                                               \
    asm volatile("mma.sync.aligned.m16n8k16.row.col.f32.f16.f16.f32 "       \
                 "{%0,%1,%2,%3}, {%4,%5,%6,%7}, {%8,%9}, {%0,%1,%2,%3};"    \
                 : "+f"((D)[0]), "+f"((D)[1]), "+f"((D)[2]), "+f"((D)[3])   \
                 : "r"((A)[0]), "r"((A)[1]), "r"((A)[2]), "r"((A)[3]),      \
                   "r"(B0), "r"(B1));

// ONE kernel: init + 2048 fused steps + decode. Grid (32, 4) x 512 threads.
__global__ __launch_bounds__(THREADS, 1)
void lstm_splitk_kernel(const float* __restrict__ x_all,
                        const float* __restrict__ h0,
                        const float* __restrict__ c0,
                        const float* __restrict__ W_ih,
                        const float* __restrict__ W_hh,
                        const float* __restrict__ b_ih,
                        const float* __restrict__ b_hh,
                        const float* __restrict__ W_dec,
                        const float* __restrict__ b_dec,
                        float* __restrict__ out)
{
    extern __shared__ __align__(16) char sm[];
    uint32_t* W      = (uint32_t*)(sm + OFF_W);
    uint32_t* Ab     = (uint32_t*)(sm + OFF_A);
    float*    gates  = (float*)   (sm + OFF_GT);    // [2][64][65]
    float*    bias_s = (float*)   (sm + OFF_BIAS);
    __shared__ unsigned s_base;

    const int tid  = threadIdx.x;
    const int lane = tid & 31, warp = tid >> 5;
    const int wm = warp & 1;          // batch half (32 rows)
    const int wn = (warp >> 1) & 3;   // 16-gatecol slice
    const int kg = warp >> 3;         // K-group (0: ks 0-3, 1: ks 4-7 of each chunk)
    const int jTile = blockIdx.x;     // 0..31
    const int bTile = blockIdx.y;     // 0..3 (= barrier group)

    if (tid == 0) s_base = g_flag[bTile][jTile];   // replay-safe monotonic base

    // ---- one-time: weights -> SMEM, single fp16 plane (K-major, padded) ----
    {
        int r = tid >> 3;                          // weight row 0..63 (tt*16+jj)
        int grow = (r >> 4) * HID + jTile * JT + (r & 15);
        int kbase = (tid & 7) * 96;
        for (int i = 0; i < 48; ++i) {
            int k = kbase + 2 * i;
            float2 v = (k < INP)
                ? *(const float2*)(W_ih + (size_t)grow * INP + k)
                : *(const float2*)(W_hh + (size_t)grow * HID + (k - INP));
            W[r * W_STRIDE + k / 2] = h2u(__floats2half2_rn(v.x, v.y));
        }
        if (tid < 64) {
            int gr = (tid >> 4) * HID + jTile * JT + (tid & 15);
            bias_s[tid] = b_ih[gr] + b_hh[gr];
        }
    }

    // ---- epilogue ownership: thread owns (eb, ej0..ej0+1); c in registers ----
    const int eb  = tid >> 3;                      // 0..63
    const int ebg = bTile * BT + eb;
    const int ej0 = (tid & 7) * 2;                 // 0..14
    const int jg0 = jTile * JT + ej0;
    const int hwi = ebg * (HID / 2) + jg0 / 2;     // one half2 word per thread
    float creg[2];
    {
        float2 cv = *(const float2*)(c0 + (size_t)ebg * HID + jg0);
        creg[0] = cv.x; creg[1] = cv.y;
        float2 hv = *(const float2*)(h0 + (size_t)ebg * HID + jg0);
        g_h[0][hwi] = h2u(__floats2half2_rn(hv.x, hv.y));
    }
    __syncthreads();
    const unsigned fbase = s_base;
    unsigned seq = 0;

#define GROUP_ARRIVE()                                                      \
    do {                                                                    \
        __syncthreads();                                                    \
        ++seq;                                                              \
        if (tid == 0) { __threadfence(); g_flag[bTile][jTile] = fbase + seq; } \
    } while (0)
#define GROUP_WAIT()                                                        \
    do {                                                                    \
        if (tid < 32) {                                                     \
            while (g_flag[bTile][tid] - fbase < seq) { }                    \
            __threadfence();                                                \
        }                                                                   \
        __syncthreads();                                                    \
    } while (0)

    GROUP_ARRIVE();   // publish h init (seq = 1)

    // ---- ldmatrix lane addressing (bytes, shared space) ----
    const uint32_t a_sh = (uint32_t)__cvta_generic_to_shared(Ab);
    const uint32_t w_sh = (uint32_t)__cvta_generic_to_shared(W);
    const int rowoff = (lane & 7) + ((lane >> 3) & 1) * 8;
    const int khalf4 = (lane >> 4) * 4;
    const uint32_t wlane = w_sh + ((wn * 16 + rowoff) * W_STRIDE + khalf4) * 4;
    uint32_t alane[2];
#pragma unroll
    for (int mf = 0; mf < 2; ++mf)
        alane[mf] = a_sh + ((wm * 32 + mf * 16 + rowoff) * A_STRIDE + khalf4) * 4;

    // staging: 8 threads per batch row, 16 k elems (8 half2 words) each
    const int srow = tid >> 3;
    const int sq   = tid & 7;
    const int sbrow = bTile * BT + srow;
    const int sdst  = srow * A_STRIDE + sq * 8;    // word offset in A plane

    for (int t = 0; t < T_STEPS; ++t) {
        const float* __restrict__ x_t = x_all + (size_t)t * BATCH * INP;
        const uint32_t* __restrict__ h_in = g_h[t & 1];
        uint32_t* __restrict__ h_out = g_h[(t & 1) ^ 1];

        float d[2][2][4];
#pragma unroll
        for (int mf = 0; mf < 2; ++mf)
#pragma unroll
            for (int nf = 0; nf < 2; ++nf)
#pragma unroll
                for (int q = 0; q < 4; ++q) d[mf][nf][q] = 0.f;

        // ---- stage chunk 0 (pure x) into buf 0 ----
        {
            const float* src = x_t + (size_t)sbrow * INP + sq * 16;
            float4 f0 = *(const float4*)(src);
            float4 f1 = *(const float4*)(src + 4);
            float4 f2 = *(const float4*)(src + 8);
            float4 f3 = *(const float4*)(src + 12);
            *(uint4*)&Ab[sdst] = make_uint4(h2u(__floats2half2_rn(f0.x, f0.y)),
                                            h2u(__floats2half2_rn(f0.z, f0.w)),
                                            h2u(__floats2half2_rn(f1.x, f1.y)),
                                            h2u(__floats2half2_rn(f1.z, f1.w)));
            *(uint4*)&Ab[sdst + 4] = make_uint4(h2u(__floats2half2_rn(f2.x, f2.y)),
                                                h2u(__floats2half2_rn(f2.z, f2.w)),
                                                h2u(__floats2half2_rn(f3.x, f3.y)),
                                                h2u(__floats2half2_rn(f3.z, f3.w)));
        }
        __syncthreads();

        int buf = 0;
        for (int c = 0; c < NCH; ++c) {
            // deferred barrier wait: h first needed by chunk 1's prefetch of chunk 2
            if (c == 1) GROUP_WAIT();

            // ---- prefetch chunk c+1 ----
            uint4 pa, pb;
            bool have_next = (c < NCH - 1);
            if (have_next) {
                int cn = c + 1;
                if (cn < 2) {   // x chunk: LDG fp32 + cvt
                    const float* src = x_t + (size_t)sbrow * INP + cn * KC + sq * 16;
                    float4 f0 = *(const float4*)(src);
                    float4 f1 = *(const float4*)(src + 4);
                    float4 f2 = *(const float4*)(src + 8);
                    float4 f3 = *(const float4*)(src + 12);
                    pa = make_uint4(h2u(__floats2half2_rn(f0.x, f0.y)),
                                    h2u(__floats2half2_rn(f0.z, f0.w)),
                                    h2u(__floats2half2_rn(f1.x, f1.y)),
                                    h2u(__floats2half2_rn(f1.z, f1.w)));
                    pb = make_uint4(h2u(__floats2half2_rn(f2.x, f2.y)),
                                    h2u(__floats2half2_rn(f2.z, f2.w)),
                                    h2u(__floats2half2_rn(f3.x, f3.y)),
                                    h2u(__floats2half2_rn(f3.z, f3.w)));
                } else {        // h chunk: already fp16 words
                    int widx = sbrow * (HID / 2) + (cn - 2) * 64 + sq * 8;
                    pa = *(const uint4*)&h_in[widx];
                    pb = *(const uint4*)&h_in[widx + 4];
                }
            }

            // ---- MMAs on chunk c: this warp's 4 k16-slices (split-K) ----
            const uint32_t aoff = (uint32_t)(buf * ABUF_BYTES);
#pragma unroll
            for (int ksl = 0; ksl < 4; ++ksl) {
                const int ks = kg * 4 + ksl;                       // 0..7 in chunk
                const uint32_t woff = (uint32_t)((c * 8 + ks) * 32);
                uint32_t bw[4];
                ldsm4(bw, wlane + woff);
#pragma unroll
                for (int mf = 0; mf < 2; ++mf) {
                    uint32_t a[4];
                    ldsm4(a, alane[mf] + aoff + (uint32_t)(ks * 32));
                    MMA_F16(d[mf][0], a, bw[0], bw[2]);
                    MMA_F16(d[mf][1], a, bw[1], bw[3]);
                }
            }

            // ---- commit prefetched chunk ----
            if (have_next) {
                int nb = buf ^ 1;
                *(uint4*)&Ab[nb * ABUF_WORDS + sdst]     = pa;
                *(uint4*)&Ab[nb * ABUF_WORDS + sdst + 4] = pb;
            }
            __syncthreads();
            buf ^= 1;
        }

        // ---- spill split-K partials to the two gate buffers ----
        {
            float* g = gates + kg * GT_WORDS;
            const int lq = lane >> 2, lr4 = lane & 3;
#pragma unroll
            for (int mf = 0; mf < 2; ++mf)
#pragma unroll
                for (int nf = 0; nf < 2; ++nf) {
                    int m = wm * 32 + mf * 16 + lq;
                    int n = wn * 16 + nf * 8 + lr4 * 2;
                    g[ m      * G_STRIDE + n    ] = d[mf][nf][0];
                    g[ m      * G_STRIDE + n + 1] = d[mf][nf][1];
                    g[(m + 8) * G_STRIDE + n    ] = d[mf][nf][2];
                    g[(m + 8) * G_STRIDE + n + 1] = d[mf][nf][3];
                }
        }
        __syncthreads();

        // ---- LSTM epilogue: sum partials, c in regs, h stored fp16 ----
        {
            float hnew[2];
#pragma unroll
            for (int i = 0; i < 2; ++i) {
                int j = ej0 + i;
                float gi = gates[eb * G_STRIDE + j]
                         + gates[GT_WORDS + eb * G_STRIDE + j]      + bias_s[j];
                float gf = gates[eb * G_STRIDE + 16 + j]
                         + gates[GT_WORDS + eb * G_STRIDE + 16 + j] + bias_s[16 + j];
                float gg = gates[eb * G_STRIDE + 32 + j]
                         + gates[GT_WORDS + eb * G_STRIDE + 32 + j] + bias_s[32 + j];
                float go = gates[eb * G_STRIDE + 48 + j]
                         + gates[GT_WORDS + eb * G_STRIDE + 48 + j] + bias_s[48 + j];
                float iv = fast_sigmoid(gi);
                float fv = fast_sigmoid(gf);
                float gv = fast_tanh(gg);
                float ov = fast_sigmoid(go);
                float cn = fv * creg[i] + iv * gv;
                creg[i] = cn;
                hnew[i] = ov * fast_tanh(cn);
            }
            h_out[hwi] = h2u(__floats2half2_rn(hnew[0], hnew[1]));
            if (t == T_STEPS - 1)
                *(float2*)&g_hf[(size_t)ebg * HID + jg0] =
                    make_float2(hnew[0], hnew[1]);
        }

        GROUP_ARRIVE();   // publish h; next step's x chunks hide the wait
    }

    GROUP_WAIT();         // final h published everywhere (for decode)

    // ---- decode by jTile==0 blocks from the fp32 h copy ----
    if (jTile == 0) {
        int b = bTile * BT + (tid >> 3);
        int part = tid & 7;
        const float* hb = g_hf + (size_t)b * HID + part * 64;
        const float* wd = W_dec + part * 64;
        float s = 0.f;
#pragma unroll 8
        for (int i = 0; i < 64; ++i) s = fmaf(hb[i], wd[i], s);
        s += __shfl_down_sync(0xFFFFFFFF, s, 4, 8);
        s += __shfl_down_sync(0xFFFFFFFF, s, 2, 8);
        s += __shfl_down_sync(0xFFFFFFFF, s, 1, 8);
        if (part == 0) out[b] = s + b_dec[0];
    }
#undef GROUP_ARRIVE
#undef GROUP_WAIT
}

extern "C" void kernel_launch(void* const* d_in, const int* in_sizes, int n_in,
                              void* d_out, int out_size)
{
    (void)in_sizes; (void)n_in; (void)out_size;
    const float* x     = (const float*)d_in[0];
    const float* h0    = (const float*)d_in[1];
    const float* c0    = (const float*)d_in[2];
    const float* W_ih  = (const float*)d_in[3];
    const float* W_hh  = (const float*)d_in[4];
    const float* b_ih  = (const float*)d_in[5];
    const float* b_hh  = (const float*)d_in[6];
    const float* W_dec = (const float*)d_in[7];
    const float* b_dec = (const float*)d_in[8];
    float* out = (float*)d_out;

    static bool attr_set = false;
    if (!attr_set) {
        cudaFuncSetAttribute(lstm_splitk_kernel,
                             cudaFuncAttributeMaxDynamicSharedMemorySize, SMEM_BYTES);
        attr_set = true;
    }

    dim3 grid(HID / JT, BATCH / BT);   // (32, 4) = 128 blocks, all co-resident
    lstm_splitk_kernel<<<grid, THREADS, SMEM_BYTES>>>(x, h0, c0, W_ih, W_hh,
                                                      b_ih, b_hh, W_dec, b_dec, out);
}

// round 16
// speedup vs baseline: 2.8699x; 1.0686x over previous
#include <cuda_runtime.h>
#include <cuda_fp16.h>
#include <stdint.h>

// Problem dims (fixed)
#define T_STEPS 2048
#define BATCH   256
#define INP     256
#define HID     512
#define KTOT    768

// Block = (jTile 0..31, bTile 0..3): 16 hidden cols x 64 batch rows; 128 blocks
#define JT 16
#define BT 64
#define THREADS 1024           // 32 warps: kg(4) x wn(4) x wm(2)
#define KC 128                 // k elems per staged chunk
#define NCH (KTOT / KC)        // 6 chunks (0-1: x, 2-5: h)
#define NBG 32                 // blocks per barrier group (one bTile)

// SMEM strides in 32-bit words (row byte-stride % 128 == 16 -> conflict-free ldsm)
#define W_STRIDE 388           // 768 fp16 = 384 words + 4 pad
#define A_STRIDE 68            // 128 fp16 = 64 words + 4 pad
#define G_STRIDE 65
#define GT_WORDS (64 * G_STRIDE)
#define ABUF_WORDS (BT * A_STRIDE)     // 4352
#define ABUF_BYTES (ABUF_WORDS * 4)    // 17408

#define OFF_W    0
#define SZ_W     (64 * W_STRIDE * 4)           // 99,328 (single fp16 plane)
#define OFF_A    SZ_W                          // 99,328
#define OFF_GT   (OFF_A + 2 * ABUF_BYTES)      // 134,144 (4 split-K gate buffers)
#define OFF_BIAS (OFF_GT + 4 * GT_WORDS * 4)   // 200,704
#define SMEM_BYTES (OFF_BIAS + 256 + 16)       // 200,976

// Persistent state: h as packed half2 words, double-buffered; fp32 copy for decode
__device__ uint32_t g_h[2][BATCH * HID / 2];
__device__ float    g_hf[BATCH * HID];
__device__ __align__(128) volatile unsigned g_flag[4][32];   // per-group barrier lines

__device__ __forceinline__ uint32_t h2u(__half2 v) {
    return *reinterpret_cast<uint32_t*>(&v);
}
__device__ __forceinline__ float fast_sigmoid(float x) {
    x = fminf(fmaxf(x, -30.f), 30.f);
    return __fdividef(1.f, 1.f + __expf(-x));
}
__device__ __forceinline__ float fast_tanh(float x) {
    x = fminf(fmaxf(x, -15.f), 15.f);
    float e = __expf(2.f * x);
    return __fdividef(e - 1.f, e + 1.f);
}
__device__ __forceinline__ void ldsm4(uint32_t* r, uint32_t saddr) {
    asm volatile("ldmatrix.sync.aligned.m8n8.x4.shared.b16 {%0,%1,%2,%3}, [%4];"
                 : "=r"(r[0]), "=r"(r[1]), "=r"(r[2]), "=r"(r[3]) : "r"(saddr));
}
#define MMA_F16(D, A, B0, B1)                                               \
    asm volatile("mma.sync.aligned.m16n8k16.row.col.f32.f16.f16.f32 "       \
                 "{%0,%1,%2,%3}, {%4,%5,%6,%7}, {%8,%9}, {%0,%1,%2,%3};"    \
                 : "+f"((D)[0]), "+f"((D)[1]), "+f"((D)[2]), "+f"((D)[3])   \
                 : "r"((A)[0]), "r"((A)[1]), "r"((A)[2]), "r"((A)[3]),      \
                   "r"(B0), "r"(B1));

// ONE kernel: init + 2048 fused steps + decode. Grid (32, 4) x 1024 threads.
__global__ __launch_bounds__(THREADS, 1)
void lstm_w32_kernel(const float* __restrict__ x_all,
                     const float* __restrict__ h0,
                     const float* __restrict__ c0,
                     const float* __restrict__ W_ih,
                     const float* __restrict__ W_hh,
                     const float* __restrict__ b_ih,
                     const float* __restrict__ b_hh,
                     const float* __restrict__ W_dec,
                     const float* __restrict__ b_dec,
                     float* __restrict__ out)
{
    extern __shared__ __align__(16) char sm[];
    uint32_t* W      = (uint32_t*)(sm + OFF_W);
    uint32_t* Ab     = (uint32_t*)(sm + OFF_A);
    float*    gates  = (float*)   (sm + OFF_GT);    // [4][64][65]
    float*    bias_s = (float*)   (sm + OFF_BIAS);
    __shared__ unsigned s_base;

    const int tid  = threadIdx.x;
    const int lane = tid & 31, warp = tid >> 5;
    const int wm = warp & 1;          // batch half (32 rows)
    const int wn = (warp >> 1) & 3;   // 16-gatecol slice
    const int kg = warp >> 3;         // K-group: 2 k16-slices per chunk each
    const int jTile = blockIdx.x;     // 0..31
    const int bTile = blockIdx.y;     // 0..3 (= barrier group)

    if (tid == 0) s_base = g_flag[bTile][jTile];   // replay-safe monotonic base

    // ---- one-time: weights -> SMEM, single fp16 plane (K-major, padded) ----
    {
        int r = tid >> 4;                          // weight row 0..63 (tt*16+jj)
        int grow = (r >> 4) * HID + jTile * JT + (r & 15);
        int kbase = (tid & 15) * 48;
        for (int i = 0; i < 24; ++i) {
            int k = kbase + 2 * i;
            float2 v = (k < INP)
                ? *(const float2*)(W_ih + (size_t)grow * INP + k)
                : *(const float2*)(W_hh + (size_t)grow * HID + (k - INP));
            W[r * W_STRIDE + k / 2] = h2u(__floats2half2_rn(v.x, v.y));
        }
        if (tid < 64) {
            int gr = (tid >> 4) * HID + jTile * JT + (tid & 15);
            bias_s[tid] = b_ih[gr] + b_hh[gr];
        }
    }

    // ---- epilogue ownership: ONE cell per thread; c in a register ----
    const int eb  = tid >> 4;                      // 0..63
    const int ebg = bTile * BT + eb;               // global batch row
    const int ej  = tid & 15;                      // hidden col within tile
    const int jg  = jTile * JT + ej;
    const int hwi = ebg * (HID / 2) + jg / 2;      // half2 word (even-ej threads store)
    float creg = c0[(size_t)ebg * HID + jg];
    if ((ej & 1) == 0) {
        float2 hv = *(const float2*)(h0 + (size_t)ebg * HID + jg);
        g_h[0][hwi] = h2u(__floats2half2_rn(hv.x, hv.y));
    }
    __syncthreads();
    const unsigned fbase = s_base;
    unsigned seq = 0;

#define GROUP_ARRIVE()                                                      \
    do {                                                                    \
        __syncthreads();                                                    \
        ++seq;                                                              \
        if (tid == 0) { __threadfence(); g_flag[bTile][jTile] = fbase + seq; } \
    } while (0)
#define GROUP_WAIT()                                                        \
    do {                                                                    \
        if (tid < 32) {                                                     \
            while (g_flag[bTile][tid] - fbase < seq) { }                    \
            __threadfence();                                                \
        }                                                                   \
        __syncthreads();                                                    \
    } while (0)

    GROUP_ARRIVE();   // publish h init (seq = 1)

    // ---- ldmatrix lane addressing (bytes, shared space) ----
    const uint32_t a_sh = (uint32_t)__cvta_generic_to_shared(Ab);
    const uint32_t w_sh = (uint32_t)__cvta_generic_to_shared(W);
    const int rowoff = (lane & 7) + ((lane >> 3) & 1) * 8;
    const int khalf4 = (lane >> 4) * 4;
    const uint32_t wlane = w_sh + ((wn * 16 + rowoff) * W_STRIDE + khalf4) * 4;
    uint32_t alane[2];
#pragma unroll
    for (int mf = 0; mf < 2; ++mf)
        alane[mf] = a_sh + ((wm * 32 + mf * 16 + rowoff) * A_STRIDE + khalf4) * 4;

    // staging: 16 threads per batch row, 8 k elems (1 uint4) each
    const int srow = tid >> 4;
    const int sq   = tid & 15;
    const int sbrow = bTile * BT + srow;
    const int sdst  = srow * A_STRIDE + sq * 4;    // word offset in A plane

    for (int t = 0; t < T_STEPS; ++t) {
        const float* __restrict__ x_t = x_all + (size_t)t * BATCH * INP;
        const uint32_t* __restrict__ h_in = g_h[t & 1];
        uint32_t* __restrict__ h_out = g_h[(t & 1) ^ 1];

        float d[2][2][4];
#pragma unroll
        for (int mf = 0; mf < 2; ++mf)
#pragma unroll
            for (int nf = 0; nf < 2; ++nf)
#pragma unroll
                for (int q = 0; q < 4; ++q) d[mf][nf][q] = 0.f;

        // ---- stage chunk 0 (pure x) into buf 0 ----
        {
            const float* src = x_t + (size_t)sbrow * INP + sq * 8;
            float4 f0 = *(const float4*)(src);
            float4 f1 = *(const float4*)(src + 4);
            *(uint4*)&Ab[sdst] = make_uint4(h2u(__floats2half2_rn(f0.x, f0.y)),
                                            h2u(__floats2half2_rn(f0.z, f0.w)),
                                            h2u(__floats2half2_rn(f1.x, f1.y)),
                                            h2u(__floats2half2_rn(f1.z, f1.w)));
        }
        __syncthreads();

        int buf = 0;
        for (int c = 0; c < NCH; ++c) {
            // deferred barrier wait: h first needed by chunk 2's prefetch
            if (c == 1) GROUP_WAIT();

            // ---- prefetch chunk c+1 (1 uint4/thread) ----
            uint4 pa;
            bool have_next = (c < NCH - 1);
            if (have_next) {
                int cn = c + 1;
                if (cn < 2) {   // x chunk: LDG fp32 + cvt
                    const float* src = x_t + (size_t)sbrow * INP + cn * KC + sq * 8;
                    float4 f0 = *(const float4*)(src);
                    float4 f1 = *(const float4*)(src + 4);
                    pa = make_uint4(h2u(__floats2half2_rn(f0.x, f0.y)),
                                    h2u(__floats2half2_rn(f0.z, f0.w)),
                                    h2u(__floats2half2_rn(f1.x, f1.y)),
                                    h2u(__floats2half2_rn(f1.z, f1.w)));
                } else {        // h chunk: already fp16 words
                    pa = *(const uint4*)&h_in[sbrow * (HID / 2) + (cn - 2) * 64 + sq * 4];
                }
            }

            // ---- MMAs on chunk c: this warp's 2 k16-slices (split-K by 4) ----
            const uint32_t aoff = (uint32_t)(buf * ABUF_BYTES);
#pragma unroll
            for (int ksl = 0; ksl < 2; ++ksl) {
                const int ks = kg * 2 + ksl;                       // 0..7 in chunk
                const uint32_t woff = (uint32_t)((c * 8 + ks) * 32);
                uint32_t bw[4];
                ldsm4(bw, wlane + woff);
#pragma unroll
                for (int mf = 0; mf < 2; ++mf) {
                    uint32_t a[4];
                    ldsm4(a, alane[mf] + aoff + (uint32_t)(ks * 32));
                    MMA_F16(d[mf][0], a, bw[0], bw[2]);
                    MMA_F16(d[mf][1], a, bw[1], bw[3]);
                }
            }

            // ---- commit prefetched chunk ----
            if (have_next)
                *(uint4*)&Ab[(buf ^ 1) * ABUF_WORDS + sdst] = pa;
            __syncthreads();
            buf ^= 1;
        }

        // ---- spill split-K partials to the four gate buffers ----
        {
            float* g = gates + kg * GT_WORDS;
            const int lq = lane >> 2, lr4 = lane & 3;
#pragma unroll
            for (int mf = 0; mf < 2; ++mf)
#pragma unroll
                for (int nf = 0; nf < 2; ++nf) {
                    int m = wm * 32 + mf * 16 + lq;
                    int n = wn * 16 + nf * 8 + lr4 * 2;
                    g[ m      * G_STRIDE + n    ] = d[mf][nf][0];
                    g[ m      * G_STRIDE + n + 1] = d[mf][nf][1];
                    g[(m + 8) * G_STRIDE + n    ] = d[mf][nf][2];
                    g[(m + 8) * G_STRIDE + n + 1] = d[mf][nf][3];
                }
        }
        __syncthreads();

        // ---- LSTM epilogue: 1 cell/thread, sum 4 partials, h packed via shfl ----
        {
            float gi = bias_s[ej],      gf = bias_s[16 + ej];
            float gg = bias_s[32 + ej], go = bias_s[48 + ej];
#pragma unroll
            for (int p = 0; p < 4; ++p) {
                const float* g = gates + p * GT_WORDS + eb * G_STRIDE;
                gi += g[ej];
                gf += g[16 + ej];
                gg += g[32 + ej];
                go += g[48 + ej];
            }
            float iv = fast_sigmoid(gi);
            float fv = fast_sigmoid(gf);
            float gv = fast_tanh(gg);
            float ov = fast_sigmoid(go);
            float cn = fv * creg + iv * gv;
            creg = cn;
            float hnew = ov * fast_tanh(cn);
            float hhi = __shfl_down_sync(0xFFFFFFFF, hnew, 1);
            if ((ej & 1) == 0)
                h_out[hwi] = h2u(__floats2half2_rn(hnew, hhi));
            if (t == T_STEPS - 1)
                g_hf[(size_t)ebg * HID + jg] = hnew;
        }

        GROUP_ARRIVE();   // publish h; next step's x chunks hide the wait
    }

    GROUP_WAIT();         // final h published everywhere (for decode)

    // ---- decode by jTile==0 blocks from the fp32 h copy ----
    if (jTile == 0) {
        int b = bTile * BT + (tid >> 4);
        int part = tid & 15;
        const float* hb = g_hf + (size_t)b * HID + part * 32;
        const float* wd = W_dec + part * 32;
        float s = 0.f;
#pragma unroll 8
        for (int i = 0; i < 32; ++i) s = fmaf(hb[i], wd[i], s);
        s += __shfl_down_sync(0xFFFFFFFF, s, 8, 16);
        s += __shfl_down_sync(0xFFFFFFFF, s, 4, 16);
        s += __shfl_down_sync(0xFFFFFFFF, s, 2, 16);
        s += __shfl_down_sync(0xFFFFFFFF, s, 1, 16);
        if (part == 0) out[b] = s + b_dec[0];
    }
#undef GROUP_ARRIVE
#undef GROUP_WAIT
}

extern "C" void kernel_launch(void* const* d_in, const int* in_sizes, int n_in,
                              void* d_out, int out_size)
{
    (void)in_sizes; (void)n_in; (void)out_size;
    const float* x     = (const float*)d_in[0];
    const float* h0    = (const float*)d_in[1];
    const float* c0    = (const float*)d_in[2];
    const float* W_ih  = (const float*)d_in[3];
    const float* W_hh  = (const float*)d_in[4];
    const float* b_ih  = (const float*)d_in[5];
    const float* b_hh  = (const float*)d_in[6];
    const float* W_dec = (const float*)d_in[7];
    const float* b_dec = (const float*)d_in[8];
    float* out = (float*)d_out;

    static bool attr_set = false;
    if (!attr_set) {
        cudaFuncSetAttribute(lstm_w32_kernel,
                             cudaFuncAttributeMaxDynamicSharedMemorySize, SMEM_BYTES);
        attr_set = true;
    }

    dim3 grid(HID / JT, BATCH / BT);   // (32, 4) = 128 blocks, all co-resident
    lstm_w32_kernel<<<grid, THREADS, SMEM_BYTES>>>(x, h0, c0, W_ih, W_hh,
                                                   b_ih, b_hh, W_dec, b_dec, out);
}